// round 1
// baseline (speedup 1.0000x reference)
#include <cuda_runtime.h>
#include <math.h>

#define NB      8192
#define TILE_B  32
#define NT      256
#define SMEM_FLOATS 24836

__device__ __forceinline__ float silu_f(float x){
    return x * (1.0f / (1.0f + __expf(-x)));
}

// Warp-cooperative top-6 of 64 values (2 per lane). Tie-break: lower index.
__device__ __forceinline__ void topk6(float p0, float p1, int lane, int* sel, float* sv){
    #pragma unroll
    for (int t = 0; t < 6; ++t){
        float v = p0; int id = lane;
        if (p1 > v){ v = p1; id = lane + 32; }
        #pragma unroll
        for (int off = 16; off > 0; off >>= 1){
            float ov = __shfl_xor_sync(0xffffffffu, v, off);
            int  oid = __shfl_xor_sync(0xffffffffu, id, off);
            if (ov > v || (ov == v && oid < id)){ v = ov; id = oid; }
        }
        sv[t] = v; sel[t] = id;
        if (id == lane)           p0 = -INFINITY;
        else if (id == lane + 32) p1 = -INFINITY;
    }
}

// One row: gumbel perturb, top-5 select, one-hot write, exact-PL log-prob.
// m, Z: max and sum-exp(l-m) of the 64 logits. All lanes return lp.
__device__ float row_topk_lp(const float* __restrict__ u,
                             const float* __restrict__ lg,
                             float m, float Z,
                             float* __restrict__ cfg,
                             int lane, int* selOut)
{
    float l0 = lg[lane], l1 = lg[lane + 32];
    float u0 = fmaxf(u[lane],      1e-10f);
    float u1 = fmaxf(u[lane + 32], 1e-10f);
    // fast gumbel (MUFU): pert = l - log(-log(u))
    float p0 = l0 - __logf(-__logf(u0));
    float p1 = l1 - __logf(-__logf(u1));
    int sel[6]; float sv[6];
    topk6(p0, p1, lane, sel, sv);
    if (sv[4] - sv[5] < 1e-4f){
        // near-boundary row: recompute gumbels in double (immune to fast-math)
        p0 = l0 - (float)log(-log((double)u0));
        p1 = l1 - (float)log(-log((double)u1));
        topk6(p0, p1, lane, sel, sv);
    }
    // one-hot config write (2 entries per lane, coalesced)
    float c0 = 0.f, c1 = 0.f;
    #pragma unroll
    for (int t = 0; t < 5; ++t){
        c0 += (sel[t] == lane)      ? 1.f : 0.f;
        c1 += (sel[t] == lane + 32) ? 1.f : 0.f;
    }
    cfg[lane]      = c0;
    cfg[lane + 32] = c1;

    // exact Plackett-Luce over 5! orderings via 2^5-subset DP:
    // lp = sum(l_sel) - 5m + log( f(empty) ),
    // f(R) = (1/(Z - E(R))) * sum_{i not in R} f(R + i),  f(full) = 1
    float lsum = 0.f, e[5];
    #pragma unroll
    for (int t = 0; t < 5; ++t){
        float lt = lg[sel[t]];
        lsum += lt;
        e[t] = expf(lt - m);
    }
    float f[32];
    f[31] = 1.f;
    #pragma unroll
    for (int mask = 30; mask >= 0; --mask){
        float Em = 0.f, s = 0.f;
        #pragma unroll
        for (int t = 0; t < 5; ++t){
            if (mask & (1 << t)) Em += e[t];
            else                 s  += f[mask | (1 << t)];
        }
        f[mask] = __fdividef(s, Z - Em);
    }
    #pragma unroll
    for (int t = 0; t < 5; ++t) selOut[t] = sel[t];
    return lsum - 5.f * m + logf(f[0]);
}

__global__ __launch_bounds__(NT, 2)
void pcf_kernel(const float* __restrict__ Ua, const float* __restrict__ Ub,
                const float* __restrict__ AL,
                const float* __restrict__ W1, const float* __restrict__ b1,
                const float* __restrict__ W2, const float* __restrict__ b2,
                const float* __restrict__ V1, const float* __restrict__ c1,
                const float* __restrict__ V2, const float* __restrict__ c2,
                const float* __restrict__ V3, const float* __restrict__ c3,
                float* __restrict__ out)
{
    extern __shared__ float sm[];
    float* s_alog = sm;                    // 64
    float* s_scal = sm + 64;               // 4
    int*   s_sela = (int*)(sm + 68);       // 160 (32 rows x 5)
    float* s_lpa  = sm + 228;              // 32   -> 260 (16B aligned)
    float* s_h    = sm + 260;              // 32x128
    float* s_x    = s_h  + TILE_B * 128;   // 32x64
    float* s_z1   = s_x  + TILE_B * 64;    // 32x256
    float* s_z2   = s_z1 + TILE_B * 256;   // 32x256
    float* s_blog = s_z2 + TILE_B * 256;   // 32x64

    const int tid  = threadIdx.x;
    const int lane = tid & 31;
    const int wid  = tid >> 5;
    const int row0 = blockIdx.x * TILE_B;

    // --- alpha logits stats (block-constant) ---
    if (wid == 0){
        float l0 = AL[lane], l1 = AL[lane + 32];
        s_alog[lane] = l0; s_alog[lane + 32] = l1;
        float mv = fmaxf(l0, l1);
        #pragma unroll
        for (int off = 16; off > 0; off >>= 1)
            mv = fmaxf(mv, __shfl_xor_sync(0xffffffffu, mv, off));
        float zv = expf(l0 - mv) + expf(l1 - mv);
        #pragma unroll
        for (int off = 16; off > 0; off >>= 1)
            zv += __shfl_xor_sync(0xffffffffu, zv, off);
        if (lane == 0){ s_scal[0] = mv; s_scal[1] = zv; }
    }
    __syncthreads();
    const float ma = s_scal[0], Za = s_scal[1];

    // --- alpha selection + lp_a (each warp handles 4 rows) ---
    for (int rr = 0; rr < 4; ++rr){
        int r = wid * 4 + rr;
        int row = row0 + r;
        int sel[5];
        float lp = row_topk_lp(Ua + (size_t)row * 64, s_alog, ma, Za,
                               out + (size_t)row * 128, lane, sel);
        if (lane == 0){
            s_lpa[r] = lp;
            #pragma unroll
            for (int t = 0; t < 5; ++t) s_sela[r * 5 + t] = sel[t];
        }
    }
    __syncthreads();

    // --- h = silu(sum of 5 W1 rows + b1) ---
    for (int i = tid; i < TILE_B * 128; i += NT){
        int r = i >> 7, j = i & 127;
        float a = b1[j];
        #pragma unroll
        for (int t = 0; t < 5; ++t) a += W1[s_sela[r * 5 + t] * 128 + j];
        s_h[i] = silu_f(a);
    }
    __syncthreads();

    // --- ctx = h @ W2 + b2  (K=128, N=64) ---
    {
        const int c = tid & 63, rg = tid >> 6;
        const float* Wp = W2 + c;
        float acc[8];
        #pragma unroll
        for (int i = 0; i < 8; i++) acc[i] = 0.f;
        for (int k = 0; k < 128; k += 4){
            float w0 = Wp[(k+0)*64], w1 = Wp[(k+1)*64];
            float w2v = Wp[(k+2)*64], w3 = Wp[(k+3)*64];
            #pragma unroll
            for (int i = 0; i < 8; i++){
                const float4 h4 = *reinterpret_cast<const float4*>(s_h + (rg*8 + i)*128 + k);
                acc[i] = fmaf(h4.x, w0, fmaf(h4.y, w1, fmaf(h4.z, w2v, fmaf(h4.w, w3, acc[i]))));
            }
        }
        float bb = b2[c];
        #pragma unroll
        for (int i = 0; i < 8; i++) s_x[(rg*8 + i)*64 + c] = acc[i] + bb;
    }
    __syncthreads();

    // --- z1 = silu(ctx @ V1[64:,:] + c1)  (K=64, N=256) ---
    {
        const int c = tid;
        const float* Vp = V1 + 64 * 256 + c;
        float acc[32];
        #pragma unroll
        for (int r = 0; r < 32; r++) acc[r] = 0.f;
        for (int k = 0; k < 64; k += 4){
            float v0 = Vp[(k+0)*256], v1 = Vp[(k+1)*256];
            float v2v = Vp[(k+2)*256], v3 = Vp[(k+3)*256];
            #pragma unroll
            for (int r = 0; r < 32; r++){
                const float4 x4 = *reinterpret_cast<const float4*>(s_x + r*64 + k);
                acc[r] = fmaf(x4.x, v0, fmaf(x4.y, v1, fmaf(x4.z, v2v, fmaf(x4.w, v3, acc[r]))));
            }
        }
        float bb = c1[c];
        #pragma unroll
        for (int r = 0; r < 32; r++) s_z1[r*256 + c] = silu_f(acc[r] + bb);
    }
    __syncthreads();

    // --- z2 = silu(z1 @ V2 + c2)  (K=256, N=256, dominant) — manual prefetch ---
    {
        const int c = tid;
        const float* Vp = V2 + c;
        float acc[32];
        #pragma unroll
        for (int r = 0; r < 32; r++) acc[r] = 0.f;
        float v0 = Vp[0], v1 = Vp[256], v2v = Vp[512], v3 = Vp[768];
        for (int kb = 0; kb < 64; ++kb){
            float n0 = 0.f, n1 = 0.f, n2 = 0.f, n3 = 0.f;
            if (kb < 63){
                const float* q = Vp + (kb + 1) * 4 * 256;
                n0 = q[0]; n1 = q[256]; n2 = q[512]; n3 = q[768];
            }
            const int k = kb * 4;
            #pragma unroll
            for (int r = 0; r < 32; r++){
                const float4 z4 = *reinterpret_cast<const float4*>(s_z1 + r*256 + k);
                acc[r] = fmaf(z4.x, v0, fmaf(z4.y, v1, fmaf(z4.z, v2v, fmaf(z4.w, v3, acc[r]))));
            }
            v0 = n0; v1 = n1; v2v = n2; v3 = n3;
        }
        float bb = c2[c];
        #pragma unroll
        for (int r = 0; r < 32; r++) s_z2[r*256 + c] = silu_f(acc[r] + bb);
    }
    __syncthreads();

    // --- beta_logits = z2 @ V3 + c3  (K=256, N=64) ---
    {
        const int c = tid & 63, rg = tid >> 6;
        const float* Vp = V3 + c;
        float acc[8];
        #pragma unroll
        for (int i = 0; i < 8; i++) acc[i] = 0.f;
        for (int k = 0; k < 256; k += 4){
            float v0 = Vp[(k+0)*64], v1 = Vp[(k+1)*64];
            float v2v = Vp[(k+2)*64], v3 = Vp[(k+3)*64];
            #pragma unroll
            for (int i = 0; i < 8; i++){
                const float4 z4 = *reinterpret_cast<const float4*>(s_z2 + (rg*8 + i)*256 + k);
                acc[i] = fmaf(z4.x, v0, fmaf(z4.y, v1, fmaf(z4.z, v2v, fmaf(z4.w, v3, acc[i]))));
            }
        }
        float bb = c3[c];
        #pragma unroll
        for (int i = 0; i < 8; i++) s_blog[(rg*8 + i)*64 + c] = acc[i] + bb;
    }
    __syncthreads();

    // --- beta selection + lp_b + final output ---
    for (int rr = 0; rr < 4; ++rr){
        int r = wid * 4 + rr;
        int row = row0 + r;
        const float* lg = s_blog + r * 64;
        float l0 = lg[lane], l1 = lg[lane + 32];
        float mv = fmaxf(l0, l1);
        #pragma unroll
        for (int off = 16; off > 0; off >>= 1)
            mv = fmaxf(mv, __shfl_xor_sync(0xffffffffu, mv, off));
        float zv = expf(l0 - mv) + expf(l1 - mv);
        #pragma unroll
        for (int off = 16; off > 0; off >>= 1)
            zv += __shfl_xor_sync(0xffffffffu, zv, off);
        int sel[5];
        float lpb = row_topk_lp(Ub + (size_t)row * 64, lg, mv, zv,
                                out + (size_t)row * 128 + 64, lane, sel);
        if (lane == 0)
            out[(size_t)NB * 128 + row] = s_lpa[r] + lpb;
    }
}

extern "C" void kernel_launch(void* const* d_in, const int* in_sizes, int n_in,
                              void* d_out, int out_size)
{
    (void)in_sizes; (void)n_in; (void)out_size;
    const float* Ua = (const float*)d_in[0];
    const float* Ub = (const float*)d_in[1];
    const float* AL = (const float*)d_in[2];
    const float* W1 = (const float*)d_in[3];
    const float* b1 = (const float*)d_in[4];
    const float* W2 = (const float*)d_in[5];
    const float* b2 = (const float*)d_in[6];
    const float* V1 = (const float*)d_in[7];
    const float* c1 = (const float*)d_in[8];
    const float* V2 = (const float*)d_in[9];
    const float* c2 = (const float*)d_in[10];
    const float* V3 = (const float*)d_in[11];
    const float* c3 = (const float*)d_in[12];
    float* out = (float*)d_out;

    const int smem_bytes = SMEM_FLOATS * (int)sizeof(float);
    cudaFuncSetAttribute(pcf_kernel, cudaFuncAttributeMaxDynamicSharedMemorySize, smem_bytes);
    pcf_kernel<<<NB / TILE_B, NT, smem_bytes>>>(Ua, Ub, AL, W1, b1, W2, b2,
                                                V1, c1, V2, c2, V3, c3, out);
}